// round 12
// baseline (speedup 1.0000x reference)
#include <cuda_runtime.h>
#include <math.h>

// Problem constants
#define BB 512
#define TT 512
#define II 8
#define HH 256

// 16 batch tiles, each an 8-CTA cluster. 128 CTAs, 1 per SM, single wave.
#define NBT 16
#define NCT 8          // CTAs per cluster (portable cluster size)
#define BT 32          // batch rows per tile/CTA
#define CT 32          // h columns per CTA (=> 96 gh cols: r,z,n)
#define NCTAS (NBT * NCT)
#define NTHREADS 256

#define WS_PITCH 65    // float4 per W row (2-phase-min bank layout)
#define WIH_PITCH 10

// SMEM layout (bytes) — identical offsets in every CTA (mbar multicast target)
#define OFF_WS   0
#define SZ_WS    (96 * WS_PITCH * 16)          // 99840
#define OFF_H0   (OFF_WS + SZ_WS)
#define SZ_H     (BT * 256 * 4)                // 32768 (8 blocks of 4KB)
#define OFF_H1   (OFF_H0 + SZ_H)
#define OFF_WLIN (OFF_H1 + SZ_H)               // 256 floats
#define OFF_WIH  (OFF_WLIN + 1024)             // 96 x WIH_PITCH floats
#define OFF_XS   (OFF_WIH + 96 * WIH_PITCH * 4)
#define OFF_BIH  (OFF_XS + BT * 8 * 4)
#define OFF_BHH  (OFF_BIH + 96 * 4)
#define OFF_MBAR (OFF_BHH + 96 * 4)            // 2 x 8B mbarriers
#define SMEM_TOTAL (OFF_MBAR + 16)

// Multicast staging: producer's slice [BT][CT], contiguous 4KB per (bt,ct)
__device__ float g_h[2][NBT][NCT][BT][CT];

__device__ __forceinline__ unsigned smem_u32(const void* p) {
    unsigned a;
    asm("{ .reg .u64 t; cvta.to.shared.u64 t, %1; cvt.u32.u64 %0, t; }"
        : "=r"(a) : "l"(p));
    return a;
}

__device__ __forceinline__ void mbar_init(unsigned addr, unsigned cnt) {
    asm volatile("mbarrier.init.shared.b64 [%0], %1;" :: "r"(addr), "r"(cnt) : "memory");
}

__device__ __forceinline__ void mbar_expect_tx(unsigned addr, unsigned bytes) {
    asm volatile("mbarrier.arrive.expect_tx.shared.b64 _, [%0], %1;"
                 :: "r"(addr), "r"(bytes) : "memory");
}

__device__ __forceinline__ void mbar_wait(unsigned addr, unsigned parity) {
    unsigned done;
    asm volatile(
        "{\n\t.reg .pred p;\n\t"
        "mbarrier.try_wait.parity.acquire.cta.shared::cta.b64 p, [%1], %2;\n\t"
        "selp.b32 %0, 1, 0, p;\n\t}"
        : "=r"(done) : "r"(addr), "r"(parity) : "memory");
    if (!done) {
        asm volatile(
            "{\n\t.reg .pred P1;\n\t"
            "WL_%=:\n\t"
            "mbarrier.try_wait.parity.acquire.cta.shared::cta.b64 P1, [%0], %1, 0x989680;\n\t"
            "@P1 bra.uni WD_%=;\n\t"
            "bra.uni WL_%=;\n\t"
            "WD_%=:\n\t}"
            :: "r"(addr), "r"(parity) : "memory");
    }
}

// Bulk multicast: 4KB global slice -> same SMEM offset in all 8 cluster CTAs,
// complete_tx lands on each CTA's local mbarrier at mbar_addr.
__device__ __forceinline__ void bulk_mcast(unsigned dst_smem, const void* src,
                                           unsigned bytes, unsigned mbar_addr,
                                           unsigned short mask) {
    asm volatile(
        "cp.async.bulk.shared::cluster.global.mbarrier::complete_tx::bytes"
        ".multicast::cluster [%0], [%1], %2, [%3], %4;"
        :: "r"(dst_smem), "l"(src), "r"(bytes), "r"(mbar_addr), "h"(mask)
        : "memory");
}

__device__ __forceinline__ float sigmoidf_fast(float v) {
    return 1.0f / (1.0f + __expf(-v));
}

__device__ __forceinline__ float tanh_fast(float v) {
    v = fminf(fmaxf(v, -15.0f), 15.0f);
    float e = __expf(-2.0f * v);
    return __fdividef(1.0f - e, 1.0f + e);
}

__device__ __forceinline__ void ffma2(unsigned long long& d,
                                      unsigned long long a,
                                      unsigned long long b) {
    asm("fma.rn.f32x2 %0, %1, %2, %0;" : "+l"(d) : "l"(a), "l"(b));
}

__device__ __forceinline__ float f2sum(unsigned long long v) {
    return __uint_as_float((unsigned)v) + __uint_as_float((unsigned)(v >> 32));
}

__global__ void __launch_bounds__(NTHREADS, 1) __cluster_dims__(NCT, 1, 1)
gru_cluster_kernel(const float* __restrict__ x,
                   const float* __restrict__ W_ih,
                   const float* __restrict__ W_hh,
                   const float* __restrict__ b_ih,
                   const float* __restrict__ b_hh,
                   const float* __restrict__ W_lin,
                   const float* __restrict__ b_lin,
                   float* __restrict__ out)
{
    extern __shared__ char sm[];
    float4* ws4   = (float4*)(sm + OFF_WS);     // [96][WS_PITCH] W_hh slice
    float*  wlin  = (float*)(sm + OFF_WLIN);    // [256]
    float*  wih   = (float*)(sm + OFF_WIH);     // [96][WIH_PITCH]
    float*  xs    = (float*)(sm + OFF_XS);      // [BT][8]
    float*  bihs  = (float*)(sm + OFF_BIH);     // [96]
    float*  bhhs  = (float*)(sm + OFF_BHH);     // [96]
    const unsigned mbar0 = smem_u32(sm + OFF_MBAR);
    const unsigned mbar1 = mbar0 + 8;
    const unsigned htile_u32[2] = { smem_u32(sm + OFF_H0), smem_u32(sm + OFF_H1) };

    const int tid = threadIdx.x;
    const int cta = blockIdx.x;
    const int bt  = cta >> 3;                    // 0..15
    const int ct  = cta & 7;                     // 0..7 (cluster rank)
    const int b0  = bt * BT;
    const int j0  = ct * CT;
    const float blin = __ldg(&b_lin[0]);

    // ---- one-time: weights into SMEM; zero h buffer 0 (h0 = 0) ----
    {
        const float4* whh4 = (const float4*)W_hh;
        for (int idx = tid; idx < 96 * 64; idx += NTHREADS) {
            int c = idx >> 6, k4 = idx & 63;
            int g = c >> 5, l = c & 31;
            int grow = g * HH + j0 + l;
            ws4[c * WS_PITCH + k4] = whh4[grow * (HH / 4) + k4];
        }
        for (int idx = tid; idx < 96 * WIH_PITCH; idx += NTHREADS) {
            int c = idx / WIH_PITCH, k = idx % WIH_PITCH;
            int g = c / 32, l = c % 32;
            int grow = g * HH + j0 + l;
            wih[idx] = (k < II) ? W_ih[grow * II + k] : 0.0f;
        }
        if (tid < 96) {
            int g = tid / 32, l = tid % 32;
            int grow = g * HH + j0 + l;
            bihs[tid] = b_ih[grow];
            bhhs[tid] = b_hh[grow];
        }
        for (int idx = tid; idx < 256; idx += NTHREADS) wlin[idx] = W_lin[idx];
        float* h0 = (float*)(sm + OFF_H0);
        for (int idx = tid; idx < BT * 256; idx += NTHREADS) h0[idx] = 0.0f;
    }

    if (tid == 0) { mbar_init(mbar0, 1); mbar_init(mbar1, 1); }
    __syncthreads();
    // mbarriers + SMEM visible cluster-wide before any multicast targets them
    asm volatile("barrier.cluster.arrive.aligned;" ::: "memory");
    asm volatile("barrier.cluster.wait.aligned;"   ::: "memory");

    // Warp layout: 8 warps = (2 col-halves) x (4 row-groups).
    // Lane: tx 0..15 (one col-triple), ty 0..1 (4 rows each).
    const int wid = tid >> 5, lane = tid & 31;
    const int half = wid & 1, rowGroup = wid >> 1;
    const int tx = lane & 15, ty = lane >> 4;
    const int rowBase = rowGroup * 8 + ty * 4;
    const int cH = half * 16 + tx;               // 0..31 local h-col

    const ulonglong2* w0q = (const ulonglong2*)(ws4 + (0 * 32 + cH) * WS_PITCH);
    const ulonglong2* w1q = (const ulonglong2*)(ws4 + (1 * 32 + cH) * WS_PITCH);
    const ulonglong2* w2q = (const ulonglong2*)(ws4 + (2 * 32 + cH) * WS_PITCH);
    const unsigned long long* wxr = (const unsigned long long*)&wih[(0 * 32 + cH) * WIH_PITCH];
    const unsigned long long* wxz = (const unsigned long long*)&wih[(1 * 32 + cH) * WIH_PITCH];
    const unsigned long long* wxn = (const unsigned long long*)&wih[(2 * 32 + cH) * WIH_PITCH];
    const float bir = bihs[cH], biz = bihs[32 + cH], bin = bihs[64 + cH];
    const float bhr = bhhs[cH], bhz = bhhs[32 + cH], bhn = bhhs[64 + cH];

    float hreg[4] = {0.f, 0.f, 0.f, 0.f};        // this thread's h (4 rows x 1 col)
    int ph[2] = {0, 0};                          // mbarrier phase parities

    for (int t = 0; t < TT; t++) {
        const int buf = t & 1, nbuf = buf ^ 1;
        const unsigned mb_buf  = buf  ? mbar1 : mbar0;
        const unsigned mb_nbuf = nbuf ? mbar1 : mbar0;
        const char* hb = sm + (buf ? OFF_H1 : OFF_H0);

        // open next phase of the receive barrier (signed-tx tolerant)
        if (tid == 0) mbar_expect_tx(mb_nbuf, SZ_H);

        // x_t tile [BT][8]
        if (tid < BT * 2) {
            int r = tid >> 1, hf = tid & 1;
            const float4* xsrc = (const float4*)&x[((size_t)(b0 + r) * TT + t) * II];
            ((float4*)xs)[r * 2 + hf] = __ldg(&xsrc[hf]);
        }

        // wait for all 8 slices of h_t (local mbarrier; t=0 uses zeroed buf0)
        if (t > 0) { mbar_wait(mb_buf, (unsigned)ph[buf]); ph[buf] ^= 1; }
        __syncthreads();

        // ---- GEMM: acc[g][i] = sum_k h[rowBase+i][k] * W_hh[g*256+j0+cH][k]
        // h tile blocked: block cb holds cols [32cb,32cb+32), row pitch 128B.
        unsigned long long acc[3][4];
        #pragma unroll
        for (int g = 0; g < 3; g++)
            #pragma unroll
            for (int i = 0; i < 4; i++) acc[g][i] = 0ull;

        #pragma unroll 2
        for (int cb = 0; cb < 8; cb++) {
            const char* hcb = hb + cb * 4096;
            const ulonglong2* h0p = (const ulonglong2*)(hcb + (rowBase + 0) * 128);
            const ulonglong2* h1p = (const ulonglong2*)(hcb + (rowBase + 1) * 128);
            const ulonglong2* h2p = (const ulonglong2*)(hcb + (rowBase + 2) * 128);
            const ulonglong2* h3p = (const ulonglong2*)(hcb + (rowBase + 3) * 128);
            #pragma unroll
            for (int kk = 0; kk < 8; kk++) {
                const int k4 = cb * 8 + kk;
                ulonglong2 w0 = w0q[k4], w1 = w1q[k4], w2 = w2q[k4];
                ulonglong2 hv0 = h0p[kk], hv1 = h1p[kk], hv2 = h2p[kk], hv3 = h3p[kk];
                ffma2(acc[0][0], hv0.x, w0.x); ffma2(acc[0][0], hv0.y, w0.y);
                ffma2(acc[1][0], hv0.x, w1.x); ffma2(acc[1][0], hv0.y, w1.y);
                ffma2(acc[2][0], hv0.x, w2.x); ffma2(acc[2][0], hv0.y, w2.y);
                ffma2(acc[0][1], hv1.x, w0.x); ffma2(acc[0][1], hv1.y, w0.y);
                ffma2(acc[1][1], hv1.x, w1.x); ffma2(acc[1][1], hv1.y, w1.y);
                ffma2(acc[2][1], hv1.x, w2.x); ffma2(acc[2][1], hv1.y, w2.y);
                ffma2(acc[0][2], hv2.x, w0.x); ffma2(acc[0][2], hv2.y, w0.y);
                ffma2(acc[1][2], hv2.x, w1.x); ffma2(acc[1][2], hv2.y, w1.y);
                ffma2(acc[2][2], hv2.x, w2.x); ffma2(acc[2][2], hv2.y, w2.y);
                ffma2(acc[0][3], hv3.x, w0.x); ffma2(acc[0][3], hv3.y, w0.y);
                ffma2(acc[1][3], hv3.x, w1.x); ffma2(acc[1][3], hv3.y, w1.y);
                ffma2(acc[2][3], hv3.x, w2.x); ffma2(acc[2][3], hv3.y, w2.y);
            }
        }

        // ---- fused gates + h update; stage slice to global for multicast ----
        float* gsl = &g_h[nbuf][bt][ct][0][0];
        #pragma unroll
        for (int i = 0; i < 4; i++) {
            const int r = rowBase + i;
            const unsigned long long* xq = (const unsigned long long*)&xs[r * II];
            unsigned long long ar = 0ull, az = 0ull, an = 0ull;
            #pragma unroll
            for (int kq = 0; kq < 4; kq++) {
                unsigned long long xv = xq[kq];
                ffma2(ar, xv, wxr[kq]);
                ffma2(az, xv, wxz[kq]);
                ffma2(an, xv, wxn[kq]);
            }
            float rr = sigmoidf_fast(bir + f2sum(ar) + f2sum(acc[0][i]) + bhr);
            float zz = sigmoidf_fast(biz + f2sum(az) + f2sum(acc[1][i]) + bhz);
            float nn = tanh_fast(bin + f2sum(an) + rr * (f2sum(acc[2][i]) + bhn));
            float hn = (1.0f - zz) * nn + zz * hreg[i];
            hreg[i] = hn;
            __stcg(&gsl[r * CT + cH], hn);
        }

        // publish: stores visible to bulk engine, then one multicast per CTA
        __threadfence();
        __syncthreads();
        if (tid == 0) {
            asm volatile("fence.proxy.async;" ::: "memory");
            bulk_mcast(htile_u32[nbuf] + (unsigned)(ct * 4096), gsl,
                       4096u, mb_nbuf, (unsigned short)0xFF);
        }

        // ---- pred[t-1] from full h_t tile (ct 7; off peers' critical path) ----
        if (ct == NCT - 1 && t > 0) {
            const int row = tid >> 3;            // 0..31
            const int oct = tid & 7;             // block cb = oct (32 cols)
            const ulonglong2* hrq =
                (const ulonglong2*)(hb + oct * 4096 + row * 128);
            const ulonglong2* wlq = (const ulonglong2*)wlin + oct * 8;
            unsigned long long a = 0ull;
            #pragma unroll
            for (int q = 0; q < 8; q++) {
                ulonglong2 hv = hrq[q], wv = wlq[q];
                ffma2(a, hv.x, wv.x);
                ffma2(a, hv.y, wv.y);
            }
            float v = f2sum(a);
            v += __shfl_xor_sync(0xffffffffu, v, 1);
            v += __shfl_xor_sync(0xffffffffu, v, 2);
            v += __shfl_xor_sync(0xffffffffu, v, 4);
            if (oct == 0)
                out[(size_t)(b0 + row) * TT + (t - 1)] = v + blin;
        }
    }

    // ---- epilogue: final h_T landed in buf0; all CTAs must absorb their
    // incoming writes before exit; ct7 emits pred[TT-1]. ----
    mbar_wait(mbar0, (unsigned)ph[0]);
    if (ct == NCT - 1) {
        const char* hb = sm + OFF_H0;
        const int row = tid >> 3;
        const int oct = tid & 7;
        const ulonglong2* hrq = (const ulonglong2*)(hb + oct * 4096 + row * 128);
        const ulonglong2* wlq = (const ulonglong2*)wlin + oct * 8;
        unsigned long long a = 0ull;
        #pragma unroll
        for (int q = 0; q < 8; q++) {
            ulonglong2 hv = hrq[q], wv = wlq[q];
            ffma2(a, hv.x, wv.x);
            ffma2(a, hv.y, wv.y);
        }
        float v = f2sum(a);
        v += __shfl_xor_sync(0xffffffffu, v, 1);
        v += __shfl_xor_sync(0xffffffffu, v, 2);
        v += __shfl_xor_sync(0xffffffffu, v, 4);
        if (oct == 0)
            out[(size_t)(b0 + row) * TT + (TT - 1)] = v + blin;
    }
    __syncthreads();
    asm volatile("barrier.cluster.arrive.aligned;" ::: "memory");
    asm volatile("barrier.cluster.wait.aligned;"   ::: "memory");
}

extern "C" void kernel_launch(void* const* d_in, const int* in_sizes, int n_in,
                              void* d_out, int out_size) {
    const float* x     = (const float*)d_in[0];
    const float* W_ih  = (const float*)d_in[1];
    const float* W_hh  = (const float*)d_in[2];
    const float* b_ih  = (const float*)d_in[3];
    const float* b_hh  = (const float*)d_in[4];
    const float* W_lin = (const float*)d_in[5];
    const float* b_lin = (const float*)d_in[6];
    float* out = (float*)d_out;

    cudaFuncSetAttribute(gru_cluster_kernel,
                         cudaFuncAttributeMaxDynamicSharedMemorySize, SMEM_TOTAL);

    gru_cluster_kernel<<<NCTAS, NTHREADS, SMEM_TOTAL>>>(
        x, W_ih, W_hh, b_ih, b_hh, W_lin, b_lin, out);
}